// round 9
// baseline (speedup 1.0000x reference)
#include <cuda_runtime.h>

// ProjectionLoss fused single-kernel. Thread = (b_local, view), 64 joints each.
// - Matrices folded per-thread from GLOBAL (no smem staging for R/t/cam/K),
//   packed as f32x2 pairs (G_i, Cm_i): gt+pred matvec = 9 fma.rn.f32x2.
// - Keypoints staged in smem (8 view-threads broadcast-share them), LDS.128.
// - One rcp per TWO points (paired perspective divide).
// - Smooth-MSE: min(d2, ex2(fma(lg2(d2), 0.1, log2(400^0.9)))) - 4 ops/term.
// - Tail: last-arriving block reduces per-block partials in fixed order.

#define B_TOTAL 16384
#define V_NUM   8
#define J_NUM   64
#define NB      16                      // batch elements per block
#define THREADS (NB * V_NUM)            // 128
#define NBLOCKS (B_TOTAL / NB)          // 1024

#define LOG2_POWC 7.77947056f           // log2(400^0.9) = 0.9*log2(400)

__device__ float g_partials[NBLOCKS];
__device__ int   g_count = 0;

typedef unsigned long long u64;

__device__ __forceinline__ u64 pk2(float lo, float hi) {
    u64 r; asm("mov.b64 %0, {%1, %2};" : "=l"(r) : "f"(lo), "f"(hi)); return r;
}
__device__ __forceinline__ void upk2(float& lo, float& hi, u64 v) {
    asm("mov.b64 {%0, %1}, %2;" : "=f"(lo), "=f"(hi) : "l"(v));
}
__device__ __forceinline__ u64 fma2(u64 a, u64 b, u64 c) {
    u64 d; asm("fma.rn.f32x2 %0, %1, %2, %3;" : "=l"(d) : "l"(a), "l"(b), "l"(c)); return d;
}
__device__ __forceinline__ float rcpa(float x) {
    float r; asm("rcp.approx.f32 %0, %1;" : "=f"(r) : "f"(x)); return r;
}
__device__ __forceinline__ float lg2a(float x) {
    float r; asm("lg2.approx.f32 %0, %1;" : "=f"(r) : "f"(x)); return r;
}
__device__ __forceinline__ float ex2a(float x) {
    float r; asm("ex2.approx.f32 %0, %1;" : "=f"(r) : "f"(x)); return r;
}
__device__ __forceinline__ float smooth_term(float d2) {
    // exact rewrite of: d2>400 ? d2^0.1 * 400^0.9 : d2 (pow branch >= d2 iff d2<=400)
    float p = ex2a(fmaf(lg2a(d2), 0.1f, LOG2_POWC));
    return fminf(d2, p);
}

__global__ __launch_bounds__(THREADS, 8)
void proj_loss_fused(const float* __restrict__ gt_kps,
                     const float* __restrict__ pr_kps,
                     const float* __restrict__ gt_R,
                     const float* __restrict__ gt_t,
                     const float* __restrict__ Kmat,
                     const float* __restrict__ cam,
                     float* __restrict__ out)
{
    __shared__ __align__(16) float sGT[NB * J_NUM * 3];   // 3072 floats
    __shared__ __align__(16) float sPR[NB * J_NUM * 3];   // 3072
    __shared__ float sWarp[THREADS / 32];
    __shared__ int   sIsLast;

    const int tid = threadIdx.x;
    const long b0 = (long)blockIdx.x * NB;

    // ---- stage keypoints to smem (float4, guarded strided) ----
    {
        const float4* g = (const float4*)(gt_kps + b0 * (J_NUM * 3));
        float4* s = (float4*)sGT;
        for (int i = tid; i < NB * J_NUM * 3 / 4; i += THREADS) s[i] = g[i];
    }
    {
        const float4* g = (const float4*)(pr_kps + b0 * (J_NUM * 3));
        float4* s = (float4*)sPR;
        for (int i = tid; i < NB * J_NUM * 3 / 4; i += THREADS) s[i] = g[i];
    }

    // ---- per-thread fold: K@[R|t] and K@cam from GLOBAL into packed regs ----
    const int bl = tid >> 3;            // 0..15
    const int v  = tid & 7;             // 0..7

    u64 GC[12];                         // (gt_coeff, pred_coeff) pairs
    {
        const float* k  = Kmat + v * 9;
        const float* R  = gt_R + (b0 + bl) * (V_NUM * 9)  + v * 9;
        const float* t  = gt_t + (b0 + bl) * (V_NUM * 3)  + v * 3;
        const float* cm = cam  + (b0 + bl) * (V_NUM * 12) + v * 12;
        #pragma unroll
        for (int r = 0; r < 3; r++) {
            float k0 = k[r * 3 + 0], k1 = k[r * 3 + 1], k2 = k[r * 3 + 2];
            #pragma unroll
            for (int c = 0; c < 3; c++) {
                float g = fmaf(k0, R[c], fmaf(k1, R[3 + c], k2 * R[6 + c]));
                float p = fmaf(k0, cm[c], fmaf(k1, cm[4 + c], k2 * cm[8 + c]));
                GC[r * 4 + c] = pk2(g, p);
            }
            float gt3 = fmaf(k0, t[0], fmaf(k1, t[1], k2 * t[2]));
            float pt3 = fmaf(k0, cm[3], fmaf(k1, cm[7], k2 * cm[11]));
            GC[r * 4 + 3] = pk2(gt3, pt3);
        }
    }

    __syncthreads();

    const float4* gt4 = (const float4*)(sGT + bl * (J_NUM * 3));  // 48 float4
    const float4* pr4 = (const float4*)(sPR + bl * (J_NUM * 3));

    float acc = 0.0f;

    // ---- main loop: 16 quads of 4 joints; packed gt/pred matvec ----
    #pragma unroll 4
    for (int jq = 0; jq < J_NUM / 4; jq++) {
        const float4 xa = gt4[jq * 3 + 0];
        const float4 xb = gt4[jq * 3 + 1];
        const float4 xc = gt4[jq * 3 + 2];
        const float4 pa = pr4[jq * 3 + 0];
        const float4 pb = pr4[jq * 3 + 1];
        const float4 pc = pr4[jq * 3 + 2];

        const float Xs[4][3] = {{xa.x, xa.y, xa.z}, {xa.w, xb.x, xb.y},
                                {xb.z, xb.w, xc.x}, {xc.y, xc.z, xc.w}};
        const float Ps[4][3] = {{pa.x, pa.y, pa.z}, {pa.w, pb.x, pb.y},
                                {pb.z, pb.w, pc.x}, {pc.y, pc.z, pc.w}};

        float us[4], ups[4], vs[4], vps[4], ws[4], wps[4];

        #pragma unroll
        for (int s = 0; s < 4; s++) {
            u64 x0 = pk2(Xs[s][0], Ps[s][0]);
            u64 x1 = pk2(Xs[s][1], Ps[s][1]);
            u64 x2 = pk2(Xs[s][2], Ps[s][2]);
            u64 uu = fma2(GC[0], x0, fma2(GC[1], x1, fma2(GC[2],  x2, GC[3])));
            u64 vv = fma2(GC[4], x0, fma2(GC[5], x1, fma2(GC[6],  x2, GC[7])));
            u64 ww = fma2(GC[8], x0, fma2(GC[9], x1, fma2(GC[10], x2, GC[11])));
            upk2(us[s], ups[s], uu);
            upk2(vs[s], vps[s], vv);
            upk2(ws[s], wps[s], ww);
        }

        // paired perspective divide: one rcp per two points
        #pragma unroll
        for (int p = 0; p < 2; p++) {
            const int a = p * 2, b = p * 2 + 1;
            float za = ws[a] * wps[a];
            float zb = ws[b] * wps[b];
            float rr = rcpa(za * zb);
            float ra = rr * zb;
            float rb = rr * za;
            float dxa = fmaf(ups[a], -ws[a], us[a] * wps[a]) * ra;
            float dya = fmaf(vps[a], -ws[a], vs[a] * wps[a]) * ra;
            float dxb = fmaf(ups[b], -ws[b], us[b] * wps[b]) * rb;
            float dyb = fmaf(vps[b], -ws[b], vs[b] * wps[b]) * rb;
            acc += smooth_term(dxa * dxa);
            acc += smooth_term(dya * dya);
            acc += smooth_term(dxb * dxb);
            acc += smooth_term(dyb * dyb);
        }
    }

    // ---- block reduction (4 warps) ----
    #pragma unroll
    for (int o = 16; o > 0; o >>= 1)
        acc += __shfl_xor_sync(0xFFFFFFFFu, acc, o);

    const int lane = tid & 31;
    const int wid  = tid >> 5;
    if (lane == 0) sWarp[wid] = acc;
    __syncthreads();

    if (wid == 0) {
        float s = (lane < THREADS / 32) ? sWarp[lane] : 0.0f;
        #pragma unroll
        for (int o = 2; o > 0; o >>= 1)
            s += __shfl_xor_sync(0xFFFFFFFFu, s, o);
        if (lane == 0) g_partials[blockIdx.x] = s;
    }

    // ---- fused finish: last-arriving block reduces partials ----
    __threadfence();
    if (tid == 0) {
        int c = atomicAdd(&g_count, 1);
        sIsLast = (c == NBLOCKS - 1);
    }
    __syncthreads();

    if (sIsLast) {
        float s = 0.0f;
        #pragma unroll
        for (int rep = 0; rep < NBLOCKS / THREADS; rep++)
            s += g_partials[tid + rep * THREADS];

        #pragma unroll
        for (int o = 16; o > 0; o >>= 1)
            s += __shfl_xor_sync(0xFFFFFFFFu, s, o);
        if (lane == 0) sWarp[wid] = s;
        __syncthreads();

        if (wid == 0) {
            float t = (lane < THREADS / 32) ? sWarp[lane] : 0.0f;
            #pragma unroll
            for (int o = 2; o > 0; o >>= 1)
                t += __shfl_xor_sync(0xFFFFFFFFu, t, o);
            if (lane == 0) {
                out[0] = t * (1.0f / (2.0f * (float)B_TOTAL));
                g_count = 0;   // reset for next graph replay
            }
        }
    }
}

extern "C" void kernel_launch(void* const* d_in, const int* in_sizes, int n_in,
                              void* d_out, int out_size)
{
    const float* gt_kps = (const float*)d_in[0];
    const float* pr_kps = (const float*)d_in[1];
    const float* gt_R   = (const float*)d_in[2];
    const float* gt_t   = (const float*)d_in[3];
    const float* Kmat   = (const float*)d_in[4];
    const float* cam    = (const float*)d_in[5];
    float* out = (float*)d_out;

    proj_loss_fused<<<NBLOCKS, THREADS>>>(gt_kps, pr_kps, gt_R, gt_t, Kmat, cam, out);
}